// round 4
// baseline (speedup 1.0000x reference)
#include <cuda_runtime.h>
#include <cstdint>

#define IN_DIM   8192
#define OUT_DIM  4096
#define BATCH    4096

// 128 MB dense-W scratch (allocation-free: __device__ global).
__device__ float g_W[(size_t)IN_DIM * OUT_DIM];
__device__ int   g_idx_is64;

// ---------------------------------------------------------------------------
// Detect whether index buffers are int64 or int32.
// If truly int64: every value < IN_DIM (8192), so the uint64 words are tiny.
// If int32 reinterpreted as uint64: high word holds the NEXT index, which is
// nonzero with prob ~1 - 1/8192 per word -> some word >= 2^16 w.p. ~1.
// ---------------------------------------------------------------------------
__global__ void detect_idx_dtype(const void* __restrict__ idx)
{
    if (threadIdx.x == 0 && blockIdx.x == 0) {
        const unsigned long long* p = (const unsigned long long*)idx;
        int is64 = 1;
        #pragma unroll
        for (int i = 0; i < 64; ++i)
            if (p[i] >= 65536ULL) is64 = 0;
        g_idx_is64 = is64;
    }
}

// ---------------------------------------------------------------------------
// Zero the dense W scratch (vectorized).
// ---------------------------------------------------------------------------
__global__ void zero_w()
{
    size_t n4 = ((size_t)IN_DIM * OUT_DIM) / 4;
    float4 z = make_float4(0.f, 0.f, 0.f, 0.f);
    float4* w4 = (float4*)g_W;
    for (size_t i = (size_t)blockIdx.x * blockDim.x + threadIdx.x;
         i < n4; i += (size_t)gridDim.x * blockDim.x)
        w4[i] = z;
}

// ---------------------------------------------------------------------------
// Scatter-add weights into dense W. Duplicates accumulate via atomicAdd.
// ---------------------------------------------------------------------------
__global__ void scatter_w(const void* __restrict__ rowp,
                          const void* __restrict__ colp,
                          const float* __restrict__ wts,
                          int nnz)
{
    const int is64 = g_idx_is64;
    for (int i = blockIdx.x * blockDim.x + threadIdx.x;
         i < nnz; i += gridDim.x * blockDim.x) {
        long long r, c;
        if (is64) {
            r = ((const long long*)rowp)[i];
            c = ((const long long*)colp)[i];
        } else {
            r = ((const int*)rowp)[i];
            c = ((const int*)colp)[i];
        }
        atomicAdd(&g_W[(size_t)r * OUT_DIM + c], wts[i]);
    }
}

// ---------------------------------------------------------------------------
// SGEMM: C[4096,4096] = x[4096,8192] @ g_W[8192,4096] + bias
// Block tile 128x128, K-tile 16, 256 threads, 8x8 per-thread micro-tile.
// ---------------------------------------------------------------------------
#define BM 128
#define BN 128
#define BK 16
#define TM 8
#define TN 8

__global__ __launch_bounds__(256, 2)
void sgemm_bias(const float* __restrict__ A,      // x, [BATCH, IN_DIM]
                const float* __restrict__ bias,   // [OUT_DIM]
                float* __restrict__ C)            // [BATCH, OUT_DIM]
{
    __shared__ float As[BK][BM];   // transposed A tile
    __shared__ float Bs[BK][BN];

    const int tid = threadIdx.x;
    const int tx  = tid & 15;      // 0..15 -> N direction
    const int ty  = tid >> 4;      // 0..15 -> M direction

    const int mBase = blockIdx.y * BM;
    const int nBase = blockIdx.x * BN;

    // A-tile loader: 128 rows x 16 cols; each thread: 2x float4
    const int aRow = tid >> 2;          // 0..63
    const int aCol = (tid & 3) * 4;     // 0,4,8,12
    // B-tile loader: 16 rows x 128 cols; each thread: 2x float4
    const int bRow = tid >> 5;          // 0..7
    const int bCol = (tid & 31) * 4;    // 0..124

    const float* Ap = A + (size_t)mBase * IN_DIM;
    const float* Bp = g_W + nBase;

    float acc[TM][TN];
    #pragma unroll
    for (int m = 0; m < TM; ++m)
        #pragma unroll
        for (int n = 0; n < TN; ++n)
            acc[m][n] = 0.f;

    for (int k0 = 0; k0 < IN_DIM; k0 += BK) {
        float4 a0 = *(const float4*)(Ap + (size_t)aRow        * IN_DIM + k0 + aCol);
        float4 a1 = *(const float4*)(Ap + (size_t)(aRow + 64) * IN_DIM + k0 + aCol);
        float4 b0 = *(const float4*)(Bp + (size_t)(k0 + bRow)     * OUT_DIM + bCol);
        float4 b1 = *(const float4*)(Bp + (size_t)(k0 + bRow + 8) * OUT_DIM + bCol);

        // transpose-store A into As[k][m]
        As[aCol + 0][aRow] = a0.x;
        As[aCol + 1][aRow] = a0.y;
        As[aCol + 2][aRow] = a0.z;
        As[aCol + 3][aRow] = a0.w;
        As[aCol + 0][aRow + 64] = a1.x;
        As[aCol + 1][aRow + 64] = a1.y;
        As[aCol + 2][aRow + 64] = a1.z;
        As[aCol + 3][aRow + 64] = a1.w;

        *(float4*)&Bs[bRow][bCol]     = b0;
        *(float4*)&Bs[bRow + 8][bCol] = b1;

        __syncthreads();

        #pragma unroll
        for (int k = 0; k < BK; ++k) {
            float ra[TM], rb[TN];
            #pragma unroll
            for (int m = 0; m < TM; ++m) ra[m] = As[k][ty * TM + m];
            #pragma unroll
            for (int n = 0; n < TN; ++n) rb[n] = Bs[k][tx * TN + n];
            #pragma unroll
            for (int m = 0; m < TM; ++m)
                #pragma unroll
                for (int n = 0; n < TN; ++n)
                    acc[m][n] = fmaf(ra[m], rb[n], acc[m][n]);
        }

        __syncthreads();
    }

    // epilogue: add bias, vectorized stores
    #pragma unroll
    for (int m = 0; m < TM; ++m) {
        const int row = mBase + ty * TM + m;
        float* cRow = C + (size_t)row * OUT_DIM + nBase + tx * TN;
        const float* bRowp = bias + nBase + tx * TN;
        #pragma unroll
        for (int n = 0; n < TN; n += 4) {
            float4 v;
            v.x = acc[m][n + 0] + bRowp[n + 0];
            v.y = acc[m][n + 1] + bRowp[n + 1];
            v.z = acc[m][n + 2] + bRowp[n + 2];
            v.w = acc[m][n + 3] + bRowp[n + 3];
            *(float4*)(cRow + n) = v;
        }
    }
}

// ---------------------------------------------------------------------------
// kernel_launch
// inputs: 0=x[f32 4096x8192], 1=row_idx, 2=col_idx, 3=weights[f32 nnz],
//         4=bias[f32 4096]; out: f32 [4096,4096]
// ---------------------------------------------------------------------------
extern "C" void kernel_launch(void* const* d_in, const int* in_sizes, int n_in,
                              void* d_out, int out_size)
{
    const float* x    = (const float*)d_in[0];
    const void*  rows = d_in[1];
    const void*  cols = d_in[2];
    const float* wts  = (const float*)d_in[3];
    const float* bias = (const float*)d_in[4];
    float* out = (float*)d_out;
    const int nnz = in_sizes[3];   // weights element count (dtype-unambiguous)

    detect_idx_dtype<<<1, 32>>>(rows);
    zero_w<<<8192, 256>>>();
    scatter_w<<<2048, 256>>>(rows, cols, wts, nnz);

    dim3 grid(OUT_DIM / BN, BATCH / BM);
    sgemm_bias<<<grid, 256>>>(x, bias, out);
}

// round 8
// speedup vs baseline: 2.5893x; 2.5893x over previous
#include <cuda_runtime.h>
#include <cuda_bf16.h>
#include <cstdint>

#define IN_DIM   8192
#define OUT_DIM  4096
#define BATCH    4096

// ---------------------------------------------------------------------------
// Device scratch (allocation-free): dense W fp32 + bf16 split operands.
// ---------------------------------------------------------------------------
__device__ float         g_W [(size_t)IN_DIM * OUT_DIM];          // 128 MB
__device__ __nv_bfloat16 g_Ah[(size_t)BATCH  * IN_DIM];           // 64 MB  x hi
__device__ __nv_bfloat16 g_Al[(size_t)BATCH  * IN_DIM];           // 64 MB  x lo
__device__ __nv_bfloat16 g_Bh[(size_t)OUT_DIM * IN_DIM];          // 64 MB  W^T hi [N,K]
__device__ __nv_bfloat16 g_Bl[(size_t)OUT_DIM * IN_DIM];          // 64 MB  W^T lo [N,K]
__device__ int           g_idx_is64;

// ---------------------------------------------------------------------------
// Helpers (base-target instructions only: cp.async, ldmatrix, mma.sync)
// ---------------------------------------------------------------------------
__device__ __forceinline__ uint32_t smem_u32(const void* p) {
    uint32_t a;
    asm("{ .reg .u64 t; cvta.to.shared.u64 t, %1; cvt.u32.u64 %0, t; }"
        : "=r"(a) : "l"(p));
    return a;
}
__device__ __forceinline__ uint32_t sw128(uint32_t o) { return o ^ ((o >> 3) & 0x70); }

__device__ __forceinline__ void cp16(uint32_t s, const void* g) {
    asm volatile("cp.async.cg.shared.global [%0], [%1], 16;" :: "r"(s), "l"(g));
}

__device__ __forceinline__ void ldsm_x4(uint32_t* r, uint32_t addr) {
    asm volatile("ldmatrix.sync.aligned.m8n8.x4.shared.b16 {%0,%1,%2,%3}, [%4];"
                 : "=r"(r[0]), "=r"(r[1]), "=r"(r[2]), "=r"(r[3]) : "r"(addr));
}

__device__ __forceinline__ void mma_bf16(float* c, const uint32_t* a,
                                         uint32_t b0, uint32_t b1) {
    asm volatile(
        "mma.sync.aligned.m16n8k16.row.col.f32.bf16.bf16.f32 "
        "{%0,%1,%2,%3}, {%4,%5,%6,%7}, {%8,%9}, {%0,%1,%2,%3};"
        : "+f"(c[0]), "+f"(c[1]), "+f"(c[2]), "+f"(c[3])
        : "r"(a[0]), "r"(a[1]), "r"(a[2]), "r"(a[3]), "r"(b0), "r"(b1));
}

// ---------------------------------------------------------------------------
// Index-dtype detection (int64 vs int32 buffers)
// ---------------------------------------------------------------------------
__global__ void detect_idx_dtype(const void* __restrict__ idx)
{
    if (threadIdx.x == 0 && blockIdx.x == 0) {
        const unsigned long long* p = (const unsigned long long*)idx;
        int is64 = 1;
        #pragma unroll
        for (int i = 0; i < 64; ++i)
            if (p[i] >= 65536ULL) is64 = 0;
        g_idx_is64 = is64;
    }
}

__global__ void zero_w()
{
    size_t n4 = ((size_t)IN_DIM * OUT_DIM) / 4;
    float4 z = make_float4(0.f, 0.f, 0.f, 0.f);
    float4* w4 = (float4*)g_W;
    for (size_t i = (size_t)blockIdx.x * blockDim.x + threadIdx.x;
         i < n4; i += (size_t)gridDim.x * blockDim.x)
        w4[i] = z;
}

__global__ void scatter_w(const void* __restrict__ rowp,
                          const void* __restrict__ colp,
                          const float* __restrict__ wts, int nnz)
{
    const int is64 = g_idx_is64;
    for (int i = blockIdx.x * blockDim.x + threadIdx.x;
         i < nnz; i += gridDim.x * blockDim.x) {
        long long r, c;
        if (is64) { r = ((const long long*)rowp)[i]; c = ((const long long*)colp)[i]; }
        else      { r = ((const int*)rowp)[i];       c = ((const int*)colp)[i]; }
        atomicAdd(&g_W[(size_t)r * OUT_DIM + c], wts[i]);
    }
}

// ---------------------------------------------------------------------------
// fp32 -> (hi, lo) bf16 split
// ---------------------------------------------------------------------------
__device__ __forceinline__ void split_bf16(float f, unsigned short& h, unsigned short& l)
{
    __nv_bfloat16 hb = __float2bfloat16_rn(f);
    float r = f - __bfloat162float(hb);
    __nv_bfloat16 lb = __float2bfloat16_rn(r);
    h = __bfloat16_as_ushort(hb);
    l = __bfloat16_as_ushort(lb);
}

__global__ void convert_x(const float4* __restrict__ x)
{
    size_t i = (size_t)blockIdx.x * blockDim.x + threadIdx.x;   // one per 8 floats
    size_t n8 = (size_t)BATCH * IN_DIM / 8;
    if (i >= n8) return;
    float4 v0 = x[2 * i], v1 = x[2 * i + 1];
    float f[8] = {v0.x, v0.y, v0.z, v0.w, v1.x, v1.y, v1.z, v1.w};
    unsigned short h[8], l[8];
    #pragma unroll
    for (int j = 0; j < 8; ++j) split_bf16(f[j], h[j], l[j]);
    uint4 uh, ul;
    uh.x = (uint32_t)h[0] | ((uint32_t)h[1] << 16);
    uh.y = (uint32_t)h[2] | ((uint32_t)h[3] << 16);
    uh.z = (uint32_t)h[4] | ((uint32_t)h[5] << 16);
    uh.w = (uint32_t)h[6] | ((uint32_t)h[7] << 16);
    ul.x = (uint32_t)l[0] | ((uint32_t)l[1] << 16);
    ul.y = (uint32_t)l[2] | ((uint32_t)l[3] << 16);
    ul.z = (uint32_t)l[4] | ((uint32_t)l[5] << 16);
    ul.w = (uint32_t)l[6] | ((uint32_t)l[7] << 16);
    ((uint4*)g_Ah)[i] = uh;
    ((uint4*)g_Al)[i] = ul;
}

// W fp32 [K, N] -> W^T bf16 split [N, K]
__global__ void convert_wT()
{
    __shared__ float t[32][33];
    int n0 = blockIdx.x * 32, k0 = blockIdx.y * 32;
    int tx = threadIdx.x, ty = threadIdx.y;        // 32 x 8
    #pragma unroll
    for (int j = 0; j < 4; ++j)
        t[ty + j * 8][tx] = g_W[(size_t)(k0 + ty + j * 8) * OUT_DIM + n0 + tx];
    __syncthreads();
    #pragma unroll
    for (int j = 0; j < 4; ++j) {
        int row = ty + j * 8;                       // local n
        float v = t[tx][row];                       // = W[k0+tx][n0+row]
        unsigned short h, l;
        split_bf16(v, h, l);
        size_t o = (size_t)(n0 + row) * IN_DIM + k0 + tx;
        g_Bh[o] = __ushort_as_bfloat16(h);
        g_Bl[o] = __ushort_as_bfloat16(l);
    }
}

// ---------------------------------------------------------------------------
// HMMA GEMM: C[4096,4096] = Ah@Bh^T + Ah@Bl^T + Al@Bh^T + bias
// Tile M=128, N=128, BK=64; 8 warps (2x4), warp tile 64x32; 2-stage cp.async.
// SW128-swizzled smem, ldmatrix.x4, mma.sync m16n8k16 bf16.
// ---------------------------------------------------------------------------
#define BM 128
#define BN 128
#define BK 64
#define NSTAGE (IN_DIM / BK)

#define STAGE_BYTES 65536
#define SM_AH(b) ((b) * STAGE_BYTES + 0)
#define SM_AL(b) ((b) * STAGE_BYTES + 16384)
#define SM_BH(b) ((b) * STAGE_BYTES + 32768)
#define SM_BL(b) ((b) * STAGE_BYTES + 49152)
#define SMEM_TOTAL (2 * STAGE_BYTES)

__device__ __forceinline__ void load_stage(uint32_t sbase, int buf,
                                           int mBase, int nBase, int k0, int tid)
{
    int r  = tid >> 3;          // 0..31
    int cc = tid & 7;           // 16B chunk within 128B row
    uint32_t so = (uint32_t)cc * 16;
    #pragma unroll
    for (int i = 0; i < 4; ++i) {                       // A: 128 rows
        int row = r + i * 32;
        size_t g = (size_t)(mBase + row) * IN_DIM + k0 + cc * 8;
        uint32_t sw = sw128((uint32_t)row * 128 + so);
        cp16(sbase + SM_AH(buf) + sw, g_Ah + g);
        cp16(sbase + SM_AL(buf) + sw, g_Al + g);
    }
    #pragma unroll
    for (int i = 0; i < 4; ++i) {                       // B: 128 rows
        int row = r + i * 32;
        size_t g = (size_t)(nBase + row) * IN_DIM + k0 + cc * 8;
        uint32_t sw = sw128((uint32_t)row * 128 + so);
        cp16(sbase + SM_BH(buf) + sw, g_Bh + g);
        cp16(sbase + SM_BL(buf) + sw, g_Bl + g);
    }
}

__global__ __launch_bounds__(256, 1)
void gemm_mma(const float* __restrict__ bias, float* __restrict__ C)
{
    extern __shared__ char smem[];
    uint32_t sbase = smem_u32(smem);
    const int tid  = threadIdx.x;
    const int wid  = tid >> 5;
    const int lane = tid & 31;
    const int nBase = blockIdx.x * BN;
    const int mBase = blockIdx.y * BM;

    const int wm0 = (wid >> 2) * 64;     // warp M offset in tile
    const int wn0 = (wid & 3) * 32;      // warp N offset in tile

    // ldmatrix per-thread addressing (SW128 over 128B rows):
    // phys = row*128 + ((k_chunk16*16) ^ ((row&7)<<4)); row&7 == lane&7 since
    // all fragment base rows are multiples of 8.
    const uint32_t row_local = (uint32_t)(((lane >> 3) & 1) * 8 + (lane & 7));
    const uint32_t c8 = (uint32_t)(lane >> 4);          // 0,1 -> k halves
    const uint32_t xr = (uint32_t)((lane & 7) << 4);

    float c[4][4][4];
    #pragma unroll
    for (int mf = 0; mf < 4; ++mf)
        #pragma unroll
        for (int nf = 0; nf < 4; ++nf)
            #pragma unroll
            for (int j = 0; j < 4; ++j) c[mf][nf][j] = 0.f;

    // Prologue: prefetch stages 0,1
    load_stage(sbase, 0, mBase, nBase, 0,  tid);
    asm volatile("cp.async.commit_group;" ::: "memory");
    load_stage(sbase, 1, mBase, nBase, BK, tid);
    asm volatile("cp.async.commit_group;" ::: "memory");

    for (int it = 0; it < NSTAGE; ++it) {
        const int buf = it & 1;
        if (it == NSTAGE - 1) asm volatile("cp.async.wait_group 0;" ::: "memory");
        else                  asm volatile("cp.async.wait_group 1;" ::: "memory");
        __syncthreads();

        const uint32_t s_ah = sbase + SM_AH(buf);
        const uint32_t s_al = sbase + SM_AL(buf);
        const uint32_t s_bh = sbase + SM_BH(buf);
        const uint32_t s_bl = sbase + SM_BL(buf);

        #pragma unroll
        for (int k16 = 0; k16 < 4; ++k16) {
            const uint32_t kterm = (((uint32_t)k16 * 32 + c8 * 16) ^ xr);

            uint32_t ah[4][4], al[4][4], bh[2][4], bl[2][4];
            #pragma unroll
            for (int mf = 0; mf < 4; ++mf) {
                uint32_t ro = (uint32_t)(wm0 + mf * 16 + row_local) * 128 + kterm;
                ldsm_x4(ah[mf], s_ah + ro);
                ldsm_x4(al[mf], s_al + ro);
            }
            #pragma unroll
            for (int nf2 = 0; nf2 < 2; ++nf2) {
                uint32_t ro = (uint32_t)(wn0 + nf2 * 16 + row_local) * 128 + kterm;
                ldsm_x4(bh[nf2], s_bh + ro);
                ldsm_x4(bl[nf2], s_bl + ro);
            }

            #pragma unroll
            for (int mf = 0; mf < 4; ++mf)
                #pragma unroll
                for (int nf = 0; nf < 4; ++nf) {
                    const int hi = nf >> 1, lo = nf & 1;
                    mma_bf16(c[mf][nf], ah[mf], bh[hi][lo], bh[hi][2 + lo]);
                    mma_bf16(c[mf][nf], ah[mf], bl[hi][lo], bl[hi][2 + lo]);
                    mma_bf16(c[mf][nf], al[mf], bh[hi][lo], bh[hi][2 + lo]);
                }
        }
        __syncthreads();

        const int next = it + 2;
        if (next < NSTAGE) {
            load_stage(sbase, buf, mBase, nBase, next * BK, tid);
            asm volatile("cp.async.commit_group;" ::: "memory");
        }
    }

    // Epilogue: add bias, store fp32 C
    const int g  = lane >> 2;
    const int tg = lane & 3;
    #pragma unroll
    for (int mf = 0; mf < 4; ++mf) {
        #pragma unroll
        for (int nf = 0; nf < 4; ++nf) {
            const int row = mBase + wm0 + mf * 16 + g;
            const int col = nBase + wn0 + nf * 8 + tg * 2;
            float2 b2 = *(const float2*)(bias + col);
            float2 v0, v1;
            v0.x = c[mf][nf][0] + b2.x;  v0.y = c[mf][nf][1] + b2.y;
            v1.x = c[mf][nf][2] + b2.x;  v1.y = c[mf][nf][3] + b2.y;
            *(float2*)(C + (size_t)row       * OUT_DIM + col) = v0;
            *(float2*)(C + (size_t)(row + 8) * OUT_DIM + col) = v1;
        }
    }
}

// ---------------------------------------------------------------------------
// kernel_launch
// inputs: 0=x[f32 4096x8192], 1=row_idx, 2=col_idx, 3=weights[f32 nnz],
//         4=bias[f32 4096]; out: f32 [4096,4096]
// ---------------------------------------------------------------------------
extern "C" void kernel_launch(void* const* d_in, const int* in_sizes, int n_in,
                              void* d_out, int out_size)
{
    const float* x    = (const float*)d_in[0];
    const void*  rows = d_in[1];
    const void*  cols = d_in[2];
    const float* wts  = (const float*)d_in[3];
    const float* bias = (const float*)d_in[4];
    float* out = (float*)d_out;
    const int nnz = in_sizes[3];

    cudaFuncSetAttribute(gemm_mma, cudaFuncAttributeMaxDynamicSharedMemorySize, SMEM_TOTAL);

    detect_idx_dtype<<<1, 32>>>(rows);
    zero_w<<<8192, 256>>>();
    scatter_w<<<2048, 256>>>(rows, cols, wts, nnz);

    convert_x<<<(BATCH * IN_DIM / 8 + 255) / 256, 256>>>((const float4*)x);
    dim3 tgrid(OUT_DIM / 32, IN_DIM / 32);
    convert_wT<<<tgrid, dim3(32, 8)>>>();

    dim3 grid(OUT_DIM / BN, BATCH / BM);
    gemm_mma<<<grid, 256, SMEM_TOTAL>>>(bias, out);
}

// round 9
// speedup vs baseline: 2.6673x; 1.0301x over previous
#include <cuda_runtime.h>
#include <cuda_bf16.h>
#include <cstdint>

#define IN_DIM   8192
#define OUT_DIM  4096
#define BATCH    4096

// ---------------------------------------------------------------------------
// Device scratch (allocation-free): dense W fp32 + bf16 split operands.
// ---------------------------------------------------------------------------
__device__ float         g_W [(size_t)IN_DIM * OUT_DIM];          // 128 MB
__device__ __nv_bfloat16 g_Ah[(size_t)BATCH  * IN_DIM];           // 64 MB  x hi
__device__ __nv_bfloat16 g_Al[(size_t)BATCH  * IN_DIM];           // 64 MB  x lo
__device__ __nv_bfloat16 g_Bh[(size_t)OUT_DIM * IN_DIM];          // 64 MB  W^T hi [N,K]
__device__ __nv_bfloat16 g_Bl[(size_t)OUT_DIM * IN_DIM];          // 64 MB  W^T lo [N,K]
__device__ int           g_idx_is64;

// ---------------------------------------------------------------------------
// Helpers (base-target instructions only: cp.async, ldmatrix, mma.sync)
// ---------------------------------------------------------------------------
__device__ __forceinline__ uint32_t smem_u32(const void* p) {
    uint32_t a;
    asm("{ .reg .u64 t; cvta.to.shared.u64 t, %1; cvt.u32.u64 %0, t; }"
        : "=r"(a) : "l"(p));
    return a;
}
__device__ __forceinline__ uint32_t sw128(uint32_t o) { return o ^ ((o >> 3) & 0x70); }

__device__ __forceinline__ void cp16(uint32_t s, const void* g) {
    asm volatile("cp.async.cg.shared.global [%0], [%1], 16;" :: "r"(s), "l"(g));
}

__device__ __forceinline__ void ldsm_x4(uint32_t* r, uint32_t addr) {
    asm volatile("ldmatrix.sync.aligned.m8n8.x4.shared.b16 {%0,%1,%2,%3}, [%4];"
                 : "=r"(r[0]), "=r"(r[1]), "=r"(r[2]), "=r"(r[3]) : "r"(addr));
}

__device__ __forceinline__ void mma_bf16(float* c, const uint32_t* a,
                                         uint32_t b0, uint32_t b1) {
    asm volatile(
        "mma.sync.aligned.m16n8k16.row.col.f32.bf16.bf16.f32 "
        "{%0,%1,%2,%3}, {%4,%5,%6,%7}, {%8,%9}, {%0,%1,%2,%3};"
        : "+f"(c[0]), "+f"(c[1]), "+f"(c[2]), "+f"(c[3])
        : "r"(a[0]), "r"(a[1]), "r"(a[2]), "r"(a[3]), "r"(b0), "r"(b1));
}

// ---------------------------------------------------------------------------
// Index-dtype detection (int64 vs int32 buffers)
// ---------------------------------------------------------------------------
__global__ void detect_idx_dtype(const void* __restrict__ idx)
{
    if (threadIdx.x == 0 && blockIdx.x == 0) {
        const unsigned long long* p = (const unsigned long long*)idx;
        int is64 = 1;
        #pragma unroll
        for (int i = 0; i < 64; ++i)
            if (p[i] >= 65536ULL) is64 = 0;
        g_idx_is64 = is64;
    }
}

__global__ void zero_w()
{
    size_t n4 = ((size_t)IN_DIM * OUT_DIM) / 4;
    float4 z = make_float4(0.f, 0.f, 0.f, 0.f);
    float4* w4 = (float4*)g_W;
    for (size_t i = (size_t)blockIdx.x * blockDim.x + threadIdx.x;
         i < n4; i += (size_t)gridDim.x * blockDim.x)
        w4[i] = z;
}

__global__ void scatter_w(const void* __restrict__ rowp,
                          const void* __restrict__ colp,
                          const float* __restrict__ wts, int nnz)
{
    const int is64 = g_idx_is64;
    for (int i = blockIdx.x * blockDim.x + threadIdx.x;
         i < nnz; i += gridDim.x * blockDim.x) {
        long long r, c;
        if (is64) { r = ((const long long*)rowp)[i]; c = ((const long long*)colp)[i]; }
        else      { r = ((const int*)rowp)[i];       c = ((const int*)colp)[i]; }
        atomicAdd(&g_W[(size_t)r * OUT_DIM + c], wts[i]);
    }
}

// ---------------------------------------------------------------------------
// fp32 -> (hi, lo) bf16 split
// ---------------------------------------------------------------------------
__device__ __forceinline__ void split_bf16(float f, unsigned short& h, unsigned short& l)
{
    __nv_bfloat16 hb = __float2bfloat16_rn(f);
    float r = f - __bfloat162float(hb);
    __nv_bfloat16 lb = __float2bfloat16_rn(r);
    h = __bfloat16_as_ushort(hb);
    l = __bfloat16_as_ushort(lb);
}

__global__ void convert_x(const float4* __restrict__ x)
{
    size_t i = (size_t)blockIdx.x * blockDim.x + threadIdx.x;   // one per 8 floats
    size_t n8 = (size_t)BATCH * IN_DIM / 8;
    if (i >= n8) return;
    float4 v0 = x[2 * i], v1 = x[2 * i + 1];
    float f[8] = {v0.x, v0.y, v0.z, v0.w, v1.x, v1.y, v1.z, v1.w};
    unsigned short h[8], l[8];
    #pragma unroll
    for (int j = 0; j < 8; ++j) split_bf16(f[j], h[j], l[j]);
    uint4 uh, ul;
    uh.x = (uint32_t)h[0] | ((uint32_t)h[1] << 16);
    uh.y = (uint32_t)h[2] | ((uint32_t)h[3] << 16);
    uh.z = (uint32_t)h[4] | ((uint32_t)h[5] << 16);
    uh.w = (uint32_t)h[6] | ((uint32_t)h[7] << 16);
    ul.x = (uint32_t)l[0] | ((uint32_t)l[1] << 16);
    ul.y = (uint32_t)l[2] | ((uint32_t)l[3] << 16);
    ul.z = (uint32_t)l[4] | ((uint32_t)l[5] << 16);
    ul.w = (uint32_t)l[6] | ((uint32_t)l[7] << 16);
    ((uint4*)g_Ah)[i] = uh;
    ((uint4*)g_Al)[i] = ul;
}

// W fp32 [K, N] -> W^T bf16 split [N, K]
__global__ void convert_wT()
{
    __shared__ float t[32][33];
    int n0 = blockIdx.x * 32, k0 = blockIdx.y * 32;
    int tx = threadIdx.x, ty = threadIdx.y;        // 32 x 8
    #pragma unroll
    for (int j = 0; j < 4; ++j)
        t[ty + j * 8][tx] = g_W[(size_t)(k0 + ty + j * 8) * OUT_DIM + n0 + tx];
    __syncthreads();
    #pragma unroll
    for (int j = 0; j < 4; ++j) {
        int row = ty + j * 8;                       // local n
        float v = t[tx][row];                       // = W[k0+tx][n0+row]
        unsigned short h, l;
        split_bf16(v, h, l);
        size_t o = (size_t)(n0 + row) * IN_DIM + k0 + tx;
        g_Bh[o] = __ushort_as_bfloat16(h);
        g_Bl[o] = __ushort_as_bfloat16(l);
    }
}

// ---------------------------------------------------------------------------
// HMMA GEMM: C[4096,4096] = Ah@Bh^T + Ah@Bl^T + Al@Bh^T + bias
// Tile M=128, N=128, BK=64; 8 warps (2x4), warp tile 64x32; 3-stage cp.async.
// MMAs issued term-major: 16 independent accumulators between reuses.
// ---------------------------------------------------------------------------
#define BM 128
#define BN 128
#define BK 64
#define NSTAGE (IN_DIM / BK)

#define STAGE_BYTES 65536
#define SM_AH(b) ((b) * STAGE_BYTES + 0)
#define SM_AL(b) ((b) * STAGE_BYTES + 16384)
#define SM_BH(b) ((b) * STAGE_BYTES + 32768)
#define SM_BL(b) ((b) * STAGE_BYTES + 49152)
#define SMEM_TOTAL (3 * STAGE_BYTES)

__device__ __forceinline__ void load_stage(uint32_t sbase, int buf,
                                           int mBase, int nBase, int k0, int tid)
{
    int r  = tid >> 3;          // 0..31
    int cc = tid & 7;           // 16B chunk within 128B row
    uint32_t so = (uint32_t)cc * 16;
    #pragma unroll
    for (int i = 0; i < 4; ++i) {                       // A: 128 rows
        int row = r + i * 32;
        size_t g = (size_t)(mBase + row) * IN_DIM + k0 + cc * 8;
        uint32_t sw = sw128((uint32_t)row * 128 + so);
        cp16(sbase + SM_AH(buf) + sw, g_Ah + g);
        cp16(sbase + SM_AL(buf) + sw, g_Al + g);
    }
    #pragma unroll
    for (int i = 0; i < 4; ++i) {                       // B: 128 rows
        int row = r + i * 32;
        size_t g = (size_t)(nBase + row) * IN_DIM + k0 + cc * 8;
        uint32_t sw = sw128((uint32_t)row * 128 + so);
        cp16(sbase + SM_BH(buf) + sw, g_Bh + g);
        cp16(sbase + SM_BL(buf) + sw, g_Bl + g);
    }
}

__global__ __launch_bounds__(256, 1)
void gemm_mma(const float* __restrict__ bias, float* __restrict__ C)
{
    extern __shared__ char smem[];
    uint32_t sbase = smem_u32(smem);
    const int tid  = threadIdx.x;
    const int wid  = tid >> 5;
    const int lane = tid & 31;
    const int nBase = blockIdx.x * BN;
    const int mBase = blockIdx.y * BM;

    const int wm0 = (wid >> 2) * 64;     // warp M offset in tile
    const int wn0 = (wid & 3) * 32;      // warp N offset in tile

    // ldmatrix per-thread addressing (SW128 over 128B rows)
    const uint32_t row_local = (uint32_t)(((lane >> 3) & 1) * 8 + (lane & 7));
    const uint32_t c8 = (uint32_t)(lane >> 4);          // 0,1 -> k halves
    const uint32_t xr = (uint32_t)((lane & 7) << 4);

    float c[4][4][4];
    #pragma unroll
    for (int mf = 0; mf < 4; ++mf)
        #pragma unroll
        for (int nf = 0; nf < 4; ++nf)
            #pragma unroll
            for (int j = 0; j < 4; ++j) c[mf][nf][j] = 0.f;

    // Prologue: prefetch stages 0,1 (stage 2 loaded inside iter 0)
    load_stage(sbase, 0, mBase, nBase, 0,  tid);
    asm volatile("cp.async.commit_group;" ::: "memory");
    load_stage(sbase, 1, mBase, nBase, BK, tid);
    asm volatile("cp.async.commit_group;" ::: "memory");

    for (int it = 0; it < NSTAGE; ++it) {
        const int buf = it % 3;
        if (it >= NSTAGE - 1) asm volatile("cp.async.wait_group 0;" ::: "memory");
        else                  asm volatile("cp.async.wait_group 1;" ::: "memory");
        __syncthreads();

        const uint32_t s_ah = sbase + SM_AH(buf);
        const uint32_t s_al = sbase + SM_AL(buf);
        const uint32_t s_bh = sbase + SM_BH(buf);
        const uint32_t s_bl = sbase + SM_BL(buf);

        #pragma unroll
        for (int k16 = 0; k16 < 4; ++k16) {
            const uint32_t kterm = (((uint32_t)k16 * 32 + c8 * 16) ^ xr);

            uint32_t ah[4][4], al[4][4], bh[2][4], bl[2][4];
            #pragma unroll
            for (int mf = 0; mf < 4; ++mf) {
                uint32_t ro = (uint32_t)(wm0 + mf * 16 + row_local) * 128 + kterm;
                ldsm_x4(ah[mf], s_ah + ro);
                ldsm_x4(al[mf], s_al + ro);
            }
            #pragma unroll
            for (int nf2 = 0; nf2 < 2; ++nf2) {
                uint32_t ro = (uint32_t)(wn0 + nf2 * 16 + row_local) * 128 + kterm;
                ldsm_x4(bh[nf2], s_bh + ro);
                ldsm_x4(bl[nf2], s_bl + ro);
            }

            // Term-major issue: 16 independent accumulators between reuses.
            #pragma unroll
            for (int mf = 0; mf < 4; ++mf)
                #pragma unroll
                for (int nf = 0; nf < 4; ++nf)
                    mma_bf16(c[mf][nf], ah[mf], bh[nf >> 1][nf & 1],
                             bh[nf >> 1][2 + (nf & 1)]);
            #pragma unroll
            for (int mf = 0; mf < 4; ++mf)
                #pragma unroll
                for (int nf = 0; nf < 4; ++nf)
                    mma_bf16(c[mf][nf], ah[mf], bl[nf >> 1][nf & 1],
                             bl[nf >> 1][2 + (nf & 1)]);
            #pragma unroll
            for (int mf = 0; mf < 4; ++mf)
                #pragma unroll
                for (int nf = 0; nf < 4; ++nf)
                    mma_bf16(c[mf][nf], al[mf], bh[nf >> 1][nf & 1],
                             bh[nf >> 1][2 + (nf & 1)]);
        }

        const int next = it + 2;
        if (next < NSTAGE) {
            // Target buffer (next%3) was last consumed at iter it-1; the
            // __syncthreads above guarantees all warps are past it.
            load_stage(sbase, next % 3, mBase, nBase, next * BK, tid);
            asm volatile("cp.async.commit_group;" ::: "memory");
        }
    }

    // Epilogue: add bias, store fp32 C
    const int g  = lane >> 2;
    const int tg = lane & 3;
    #pragma unroll
    for (int mf = 0; mf < 4; ++mf) {
        #pragma unroll
        for (int nf = 0; nf < 4; ++nf) {
            const int row = mBase + wm0 + mf * 16 + g;
            const int col = nBase + wn0 + nf * 8 + tg * 2;
            float2 b2 = *(const float2*)(bias + col);
            float2 v0, v1;
            v0.x = c[mf][nf][0] + b2.x;  v0.y = c[mf][nf][1] + b2.y;
            v1.x = c[mf][nf][2] + b2.x;  v1.y = c[mf][nf][3] + b2.y;
            *(float2*)(C + (size_t)row       * OUT_DIM + col) = v0;
            *(float2*)(C + (size_t)(row + 8) * OUT_DIM + col) = v1;
        }
    }
}

// ---------------------------------------------------------------------------
// kernel_launch
// inputs: 0=x[f32 4096x8192], 1=row_idx, 2=col_idx, 3=weights[f32 nnz],
//         4=bias[f32 4096]; out: f32 [4096,4096]
// ---------------------------------------------------------------------------
extern "C" void kernel_launch(void* const* d_in, const int* in_sizes, int n_in,
                              void* d_out, int out_size)
{
    const float* x    = (const float*)d_in[0];
    const void*  rows = d_in[1];
    const void*  cols = d_in[2];
    const float* wts  = (const float*)d_in[3];
    const float* bias = (const float*)d_in[4];
    float* out = (float*)d_out;
    const int nnz = in_sizes[3];

    cudaFuncSetAttribute(gemm_mma, cudaFuncAttributeMaxDynamicSharedMemorySize, SMEM_TOTAL);

    detect_idx_dtype<<<1, 32>>>(rows);
    zero_w<<<8192, 256>>>();
    scatter_w<<<2048, 256>>>(rows, cols, wts, nnz);

    convert_x<<<(BATCH * IN_DIM / 8 + 255) / 256, 256>>>((const float4*)x);
    dim3 tgrid(OUT_DIM / 32, IN_DIM / 32);
    convert_wT<<<tgrid, dim3(32, 8)>>>();

    dim3 grid(OUT_DIM / BN, BATCH / BM);
    gemm_mma<<<grid, 256, SMEM_TOTAL>>>(bias, out);
}